// round 6
// baseline (speedup 1.0000x reference)
#include <cuda_runtime.h>
#include <cuda_bf16.h>
#include <cstdint>

#if defined(__CUDA_ARCH_FEAT_SM103_ALL) || defined(__CUDA_ARCH_FEAT_SM100_ALL) || defined(__CUDA_ARCH_FEAT_SM101_ALL)
#define TC_OK 1
#else
#define TC_OK 0
#endif

// ---------------- problem constants ----------------
#define T_TOK 8192
#define H_DIM 2048
#define DFF   8192
#define NE    8
#define CAP   8192
#define NPAIR (T_TOK * 2)

// ---------------- scratch (device globals) ----------------
__device__ __nv_bfloat16 g_xh[(size_t)T_TOK * H_DIM];
__device__ __nv_bfloat16 g_xl[(size_t)T_TOK * H_DIM];
__device__ __nv_bfloat16 g_w1th[(size_t)NE * DFF * H_DIM];
__device__ __nv_bfloat16 g_w1tl[(size_t)NE * DFF * H_DIM];
__device__ __nv_bfloat16 g_w2th[(size_t)NE * H_DIM * DFF];
__device__ __nv_bfloat16 g_w2tl[(size_t)NE * H_DIM * DFF];
__device__ __nv_bfloat16 g_hh[(size_t)NPAIR * DFF];
__device__ __nv_bfloat16 g_hl[(size_t)NPAIR * DFF];
__device__ float g_yslot[(size_t)NPAIR * H_DIM];
__device__ int   g_list[NE * CAP];
__device__ float g_wt[NPAIR];
__device__ int   g_counts[NE];
__device__ int   g_off[NE];

// ---------------- scalar helpers ----------------
__device__ __forceinline__ float fast_tanh(float v) {
    float r; asm("tanh.approx.f32 %0, %1;" : "=f"(r) : "f"(v)); return r;
}
__device__ __forceinline__ float gelu_tanh(float v) {
    float u = 0.7978845608028654f * (v + 0.044715f * v * v * v);
    return 0.5f * v * (1.0f + fast_tanh(u));
}
__device__ __forceinline__ uint32_t pack_bf2(__nv_bfloat16 a, __nv_bfloat16 b) {
    __nv_bfloat162 p = __halves2bfloat162(a, b);
    return *reinterpret_cast<uint32_t*>(&p);
}
__device__ __forceinline__ void split2(float v, __nv_bfloat16& h, __nv_bfloat16& l) {
    h = __float2bfloat16(v);
    l = __float2bfloat16(v - __bfloat162float(h));
}

// ---------------- family-safe PTX helpers ----------------
__device__ __forceinline__ void cp16(void* dst, const void* src) {
    uint32_t d = (uint32_t)__cvta_generic_to_shared(dst);
    asm volatile("cp.async.cg.shared.global [%0], [%1], 16;" :: "r"(d), "l"(src));
}
__device__ __forceinline__ void cp_commit() { asm volatile("cp.async.commit_group;"); }
__device__ __forceinline__ void cp_wait1() { asm volatile("cp.async.wait_group 1;"); }
__device__ __forceinline__ void cp_wait0() { asm volatile("cp.async.wait_group 0;"); }

__device__ __forceinline__ uint32_t elect_one() {
    uint32_t pred;
    asm volatile("{\n\t.reg .pred p;\n\telect.sync _|p, 0xFFFFFFFF;\n\t"
                 "selp.b32 %0, 1, 0, p;\n\t}" : "=r"(pred));
    return pred;
}
__device__ __forceinline__ void fence_proxy_async_full() {
    asm volatile("fence.proxy.async;" ::: "memory");
}
__device__ __forceinline__ void mbar_init(uint32_t a, uint32_t cnt) {
    asm volatile("mbarrier.init.shared.b64 [%0], %1;" :: "r"(a), "r"(cnt) : "memory");
}
__device__ __forceinline__ void mbar_inval(uint32_t a) {
    asm volatile("mbarrier.inval.shared.b64 [%0];" :: "r"(a) : "memory");
}
__device__ __forceinline__ void mbar_wait(uint32_t a, uint32_t parity) {
    uint32_t done;
    asm volatile("{\n\t.reg .pred p;\n\t"
                 "mbarrier.try_wait.parity.acquire.cta.shared::cta.b64 p, [%1], %2;\n\t"
                 "selp.b32 %0, 1, 0, p;\n\t}"
                 : "=r"(done) : "r"(a), "r"(parity) : "memory");
    if (!done) {
        asm volatile("{\n\t.reg .pred P1;\n\t"
                     "W_%=:\n\t"
                     "mbarrier.try_wait.parity.acquire.cta.shared::cta.b64 P1, [%0], %1, 0x989680;\n\t"
                     "@P1 bra.uni D_%=;\n\t"
                     "bra.uni W_%=;\n\t"
                     "D_%=:\n\t}"
                     :: "r"(a), "r"(parity) : "memory");
    }
}
__device__ __forceinline__ void mbar_wait_cluster(uint32_t a, uint32_t parity) {
    asm volatile("{\n\t.reg .pred P1;\n\t"
                 "W_%=:\n\t"
                 "mbarrier.try_wait.parity.acquire.cluster.shared::cta.b64 P1, [%0], %1, 0x989680;\n\t"
                 "@P1 bra.uni D_%=;\n\t"
                 "bra.uni W_%=;\n\t"
                 "D_%=:\n\t}"
                 :: "r"(a), "r"(parity) : "memory");
}
__device__ __forceinline__ void mbar_arrive_local(uint32_t a) {
    asm volatile("mbarrier.arrive.shared.b64 _, [%0];" :: "r"(a) : "memory");
}
__device__ __forceinline__ void mbar_arrive_cluster_rank(uint32_t a, uint32_t rank) {
    asm volatile("{\n\t.reg .b32 r;\n\t"
                 "mapa.shared::cluster.u32 r, %0, %1;\n\t"
                 "mbarrier.arrive.shared::cluster.b64 _, [r];\n\t}"
                 :: "r"(a), "r"(rank) : "memory");
}
__device__ __forceinline__ void cluster_sync_all() {
    asm volatile("barrier.cluster.arrive.aligned;" ::: "memory");
    asm volatile("barrier.cluster.wait.aligned;" ::: "memory");
}
__device__ __forceinline__ uint32_t ctarank() {
    uint32_t r; asm("mov.u32 %0, %%cluster_ctarank;" : "=r"(r)); return r;
}

#define SW64(x) ((x) ^ (((x) >> 3) & 0x30))

// ---------------- routing kernels ----------------
__global__ void zero_counts_kernel() {
    if (threadIdx.x < NE) g_counts[threadIdx.x] = 0;
}

__global__ void router_kernel(const float* __restrict__ x,
                              const float* __restrict__ wg,
                              float* __restrict__ logits_out) {
    int t = blockIdx.x * (blockDim.x >> 5) + (threadIdx.x >> 5);
    int lane = threadIdx.x & 31;
    if (t >= T_TOK) return;
    const float* xr = x + (size_t)t * H_DIM;
    float acc[NE];
#pragma unroll
    for (int e = 0; e < NE; e++) acc[e] = 0.0f;
    for (int h = lane; h < H_DIM; h += 32) {
        float xv = xr[h];
        const float4* w4 = reinterpret_cast<const float4*>(wg + (size_t)h * NE);
        float4 a = w4[0], b = w4[1];
        acc[0] += xv * a.x; acc[1] += xv * a.y; acc[2] += xv * a.z; acc[3] += xv * a.w;
        acc[4] += xv * b.x; acc[5] += xv * b.y; acc[6] += xv * b.z; acc[7] += xv * b.w;
    }
#pragma unroll
    for (int e = 0; e < NE; e++)
#pragma unroll
        for (int o = 16; o > 0; o >>= 1)
            acc[e] += __shfl_xor_sync(0xffffffffu, acc[e], o);
    if (lane == 0) {
#pragma unroll
        for (int e = 0; e < NE; e++) logits_out[(size_t)t * NE + e] = acc[e];
        float m = acc[0];
#pragma unroll
        for (int e = 1; e < NE; e++) m = fmaxf(m, acc[e]);
        float p[NE], s = 0.0f;
#pragma unroll
        for (int e = 0; e < NE; e++) { p[e] = expf(acc[e] - m); s += p[e]; }
        float inv = 1.0f / s;
        int i0 = 0;
#pragma unroll
        for (int e = 1; e < NE; e++) if (acc[e] > acc[i0]) i0 = e;
        int i1 = (i0 == 0) ? 1 : 0;
#pragma unroll
        for (int e = 0; e < NE; e++) if (e != i0 && acc[e] > acc[i1]) i1 = e;
        int p0 = t * 2, p1 = t * 2 + 1;
        g_wt[p0] = p[i0] * inv;
        g_wt[p1] = p[i1] * inv;
        int pos0 = atomicAdd(&g_counts[i0], 1);
        g_list[i0 * CAP + pos0] = p0;
        int pos1 = atomicAdd(&g_counts[i1], 1);
        g_list[i1 * CAP + pos1] = p1;
    }
}

__global__ void offsets_kernel() {
    if (threadIdx.x == 0) {
        int s = 0;
#pragma unroll
        for (int e = 0; e < NE; e++) { g_off[e] = s; s += g_counts[e]; }
    }
}

// ---------------- split x (fp32 -> bf16 hi + lo) ----------------
__global__ void split_kernel(const float* __restrict__ s,
                             __nv_bfloat16* __restrict__ h,
                             __nv_bfloat16* __restrict__ l, size_t n4) {
    size_t i = (size_t)blockIdx.x * blockDim.x + threadIdx.x;
    if (i >= n4) return;
    float4 v = reinterpret_cast<const float4*>(s)[i];
    __nv_bfloat16 h0, l0, h1, l1, h2, l2, h3, l3;
    split2(v.x, h0, l0); split2(v.y, h1, l1);
    split2(v.z, h2, l2); split2(v.w, h3, l3);
    uint2 hv, lv;
    hv.x = pack_bf2(h0, h1); hv.y = pack_bf2(h2, h3);
    lv.x = pack_bf2(l0, l1); lv.y = pack_bf2(l2, l3);
    reinterpret_cast<uint2*>(h)[i] = hv;
    reinterpret_cast<uint2*>(l)[i] = lv;
}

// ---------------- transpose + split: W[e][K][N] -> Wt(h/l)[e][N][K] ----------------
__global__ void transpose_split_kernel(const float* __restrict__ src,
                                       __nv_bfloat16* __restrict__ dh,
                                       __nv_bfloat16* __restrict__ dl,
                                       int K, int N) {
    __shared__ float tile[32][33];
    int e = blockIdx.z;
    const float* S = src + (size_t)e * K * N;
    int n0 = blockIdx.x * 32, k0 = blockIdx.y * 32;
#pragma unroll
    for (int i = threadIdx.y; i < 32; i += 8)
        tile[i][threadIdx.x] = S[(size_t)(k0 + i) * N + n0 + threadIdx.x];
    __syncthreads();
    __nv_bfloat16* Dh = dh + (size_t)e * K * N;
    __nv_bfloat16* Dl = dl + (size_t)e * K * N;
#pragma unroll
    for (int i = threadIdx.y; i < 32; i += 8) {
        float v = tile[threadIdx.x][i];
        __nv_bfloat16 h, l;
        split2(v, h, l);
        size_t o = (size_t)(n0 + i) * K + k0 + threadIdx.x;
        Dh[o] = h;
        Dl[o] = l;
    }
}

// ---------------- cg2 tcgen05 GEMM: pair tile 512x256, BK=32, SW64, 2-stage ----------------
#define TM_PAIR 512          // M rows per 2-CTA pair
#define TM_CTA  256          // A rows per CTA (two 128-row M-subtiles)
#define TN      256          // N cols (B: 128 rows per CTA)
#define TBK     32
#define TILE_A  16384        // 256 rows x 64B
#define TILE_B  8192         // 128 rows x 64B
#define STAGE_BYTES (2 * TILE_A + 2 * TILE_B)   // 49152
#define SMEM_DYN (2 * STAGE_BYTES)              // 98304

#if TC_OK
__device__ __forceinline__ uint64_t sw64_desc(uint32_t addr) {
    uint64_t d = 0;
    d |= (uint64_t)((addr >> 4) & 0x3FFF);
    d |= (uint64_t)1  << 16;
    d |= (uint64_t)32 << 32;
    d |= (uint64_t)1  << 46;
    d |= (uint64_t)4  << 61;
    return d;
}

// idesc kind::f16 cg2: dtype F32, a/b BF16, M=256 (16<<24), N=256 (32<<17)
#define IDESC_CG2 ((16u << 24) | (32u << 17) | (1u << 10) | (1u << 7) | (1u << 4))

__device__ __forceinline__ void mma_f16_ss_cg2(uint32_t d, uint64_t ad, uint64_t bd,
                                               uint32_t en) {
    asm volatile(
        "{\n\t.reg .pred p;\n\tsetp.ne.u32 p, %4, 0;\n\t"
        "tcgen05.mma.cta_group::2.kind::f16 [%0], %1, %2, %3, "
        "{%5,%5,%5,%5,%5,%5,%5,%5}, p;\n\t}"
        :: "r"(d), "l"(ad), "l"(bd), "r"(IDESC_CG2), "r"(en), "r"(0u) : "memory");
}
__device__ __forceinline__ void tc_alloc_cg2(uint32_t smem_slot, uint32_t ncols) {
    asm volatile("tcgen05.alloc.cta_group::2.sync.aligned.shared::cta.b32 [%0], %1;"
                 :: "r"(smem_slot), "r"(ncols) : "memory");
}
__device__ __forceinline__ void tc_relinquish_cg2() {
    asm volatile("tcgen05.relinquish_alloc_permit.cta_group::2.sync.aligned;");
}
__device__ __forceinline__ void tc_dealloc_cg2(uint32_t tmem, uint32_t ncols) {
    asm volatile("tcgen05.dealloc.cta_group::2.sync.aligned.b32 %0, %1;"
                 :: "r"(tmem), "r"(ncols));
}
__device__ __forceinline__ void tc_commit_mc_cg2(uint32_t mbar, uint16_t mask) {
    asm volatile("tcgen05.commit.cta_group::2.mbarrier::arrive::one.shared::cluster.multicast::cluster.b64 [%0], %1;"
                 :: "r"(mbar), "h"(mask) : "memory");
}
__device__ __forceinline__ void tc_fence_after() {
    asm volatile("tcgen05.fence::after_thread_sync;" ::: "memory");
}
__device__ __forceinline__ void tmem_ld32(uint32_t* r, uint32_t addr) {
    asm volatile(
        "tcgen05.ld.sync.aligned.32x32b.x32.b32 "
        "{%0,%1,%2,%3,%4,%5,%6,%7,%8,%9,%10,%11,%12,%13,%14,%15,"
        "%16,%17,%18,%19,%20,%21,%22,%23,%24,%25,%26,%27,%28,%29,%30,%31}, [%32];"
        : "=r"(r[0]), "=r"(r[1]), "=r"(r[2]), "=r"(r[3]), "=r"(r[4]), "=r"(r[5]),
          "=r"(r[6]), "=r"(r[7]), "=r"(r[8]), "=r"(r[9]), "=r"(r[10]), "=r"(r[11]),
          "=r"(r[12]), "=r"(r[13]), "=r"(r[14]), "=r"(r[15]), "=r"(r[16]), "=r"(r[17]),
          "=r"(r[18]), "=r"(r[19]), "=r"(r[20]), "=r"(r[21]), "=r"(r[22]), "=r"(r[23]),
          "=r"(r[24]), "=r"(r[25]), "=r"(r[26]), "=r"(r[27]), "=r"(r[28]), "=r"(r[29]),
          "=r"(r[30]), "=r"(r[31])
        : "r"(addr));
}
__device__ __forceinline__ void tmem_wait_ld() {
    asm volatile("tcgen05.wait::ld.sync.aligned;" ::: "memory");
}

// fill one stage: A = 256 gathered rows (this CTA's halves of both M-subtiles),
// B = 128 rows (this CTA's N half)
__device__ __forceinline__ void fill_stage(
    char* st, const size_t* rowsrc,
    const __nv_bfloat16* Ah, const __nv_bfloat16* Al,
    const __nv_bfloat16* Bh, const __nv_bfloat16* Bl,
    size_t bbase, size_t ldk, int kt, int tid)
{
    char* sAh = st;
    char* sAl = st + TILE_A;
    char* sBh = st + 2 * TILE_A;
    char* sBl = st + 2 * TILE_A + TILE_B;
#pragma unroll
    for (int it = 0; it < 4; it++) {
        int f = tid + it * 256;
        int row = f >> 2, c = f & 3;
        uint32_t doff = SW64(row * 64 + c * 16);
        size_t asrc = rowsrc[row] + kt + c * 8;
        cp16(sAh + doff, Ah + asrc);
        cp16(sAl + doff, Al + asrc);
    }
#pragma unroll
    for (int it = 0; it < 2; it++) {
        int f = tid + it * 256;
        int row = f >> 2, c = f & 3;
        uint32_t doff = SW64(row * 64 + c * 16);
        size_t bsrc = bbase + (size_t)row * ldk + kt + c * 8;
        cp16(sBh + doff, Bh + bsrc);
        cp16(sBl + doff, Bl + bsrc);
    }
}

// mainloop; on return TMEM D holds [2 M-subs x 128 lanes x 256 cols] per CTA
// mbar layout (smem u64 array): [0]=done0 [1]=done1 [2]=ready0 [3]=ready1
__device__ __forceinline__ void run_mainloop_cg2(
    char* dyn, const size_t* rowsrc,
    const __nv_bfloat16* Ah, const __nv_bfloat16* Al,
    const __nv_bfloat16* Bh, const __nv_bfloat16* Bl,
    size_t bbase, size_t ldk, int KIT,
    uint32_t tmem_base, uint32_t mbar0, int tid, uint32_t rank)
{
    fill_stage(dyn, rowsrc, Ah, Al, Bh, Bl, bbase, ldk, 0, tid);
    cp_commit();
    fill_stage(dyn + STAGE_BYTES, rowsrc, Ah, Al, Bh, Bl, bbase, ldk, TBK, tid);
    cp_commit();

    uint32_t dynb = (uint32_t)__cvta_generic_to_shared(dyn);
    int phd0 = 0, phd1 = 0;       // done-bar parities (refill waits)
    int phr0 = 0, phr1 = 0;       // ready-bar parities (leader)
    bool leader_warp = (rank == 0) && ((tid >> 5) == 0);

    for (int ki = 0; ki < KIT; ki++) {
        int s = ki & 1;
        if (ki + 1 < KIT) cp_wait1(); else cp_wait0();
        __syncthreads();
        if (tid == 0) {
            fence_proxy_async_full();
            if (rank == 0) mbar_arrive_local(mbar0 + 16 + s * 8);
            else           mbar_arrive_cluster_rank(mbar0 + 16 + s * 8, 0);
        }
        if (leader_warp) {
            if (elect_one()) {
                int phr = s ? phr1 : phr0;
                mbar_wait_cluster(mbar0 + 16 + s * 8, phr);
                uint32_t base = dynb + s * STAGE_BYTES;
                uint64_t dA  = sw64_desc(base);
                uint64_t dAl = sw64_desc(base + TILE_A);
                uint64_t dBh = sw64_desc(base + 2 * TILE_A);
                uint64_t dBl = sw64_desc(base + 2 * TILE_A + TILE_B);
#pragma unroll
                for (int sub = 0; sub < 2; sub++) {
                    uint32_t d = tmem_base + sub * 256;
                    uint32_t aoff = sub * 512;   // +128 rows * 64B / 16
#pragma unroll
                    for (int c = 0; c < 2; c++) {
                        uint32_t en0 = (ki > 0 || c > 0) ? 1u : 0u;
                        mma_f16_ss_cg2(d, dA  + aoff + c * 2, dBh + c * 2, en0);
                        mma_f16_ss_cg2(d, dAl + aoff + c * 2, dBh + c * 2, 1u);
                        mma_f16_ss_cg2(d, dA  + aoff + c * 2, dBl + c * 2, 1u);
                    }
                }
                tc_commit_mc_cg2(mbar0 + s * 8, 0x3);
            }
            if (s) phr1 ^= 1; else phr0 ^= 1;
        }
        if (ki + 2 < KIT) {
            int phd = s ? phd1 : phd0;
            mbar_wait(mbar0 + s * 8, phd);
            if (s) phd1 ^= 1; else phd0 ^= 1;
            fill_stage(dyn + s * STAGE_BYTES, rowsrc, Ah, Al, Bh, Bl,
                       bbase, ldk, (ki + 2) * TBK, tid);
            cp_commit();
        }
    }
    int sl = (KIT - 1) & 1;
    mbar_wait(mbar0 + sl * 8, sl ? phd1 : phd0);
    tc_fence_after();
    __syncthreads();
}
#endif  // TC_OK

// GEMM1: hmid(hi/lo) = split(gelu( x @ w1t^T )), pair tile 512x256
__global__ __launch_bounds__(256, 1) __cluster_dims__(2, 1, 1)
void gemm1_kernel() {
#if TC_OK
    extern __shared__ __align__(1024) char dyn[];
    __shared__ __align__(16) unsigned long long mbars[4];
    __shared__ uint32_t tmem_slot;
    __shared__ size_t rowsrc[TM_CTA];

    int e = blockIdx.z;
    int cnt = g_counts[e];
    uint32_t rank = ctarank();                    // = blockIdx.x & 1
    int m0 = blockIdx.y * TM_PAIR;
    if (m0 >= cnt) return;                        // both CTAs of pair exit together
    int n0 = (blockIdx.x >> 1) * TN;
    int off = g_off[e];
    int tid = threadIdx.x;

    uint32_t mbar0 = (uint32_t)__cvta_generic_to_shared(&mbars[0]);
    uint32_t slot  = (uint32_t)__cvta_generic_to_shared(&tmem_slot);

    if ((tid >> 5) == 0) tc_alloc_cg2(slot, 512);
    if (tid == 0) {
        mbar_init(mbar0, 1);       mbar_init(mbar0 + 8, 1);    // done (commit-mc)
        mbar_init(mbar0 + 16, 2);  mbar_init(mbar0 + 24, 2);   // ready (2 arrivals)
    }
    if (tid < TM_CTA) {
        // smem A row i -> global list index m0 + (i>>7)*256 + rank*128 + (i&127)
        int gm = m0 + ((tid >> 7) << 8) + (int)rank * 128 + (tid & 127);
        int gmc = (gm < cnt) ? gm : (cnt - 1);
        rowsrc[tid] = (size_t)(g_list[e * CAP + gmc] >> 1) * H_DIM;
    }
    __syncthreads();
    if ((tid >> 5) == 0) tc_relinquish_cg2();
    cluster_sync_all();                           // mbars + peer smem valid before cg2 ops
    uint32_t tmem_base = tmem_slot;

    // B: this CTA's N-half rows [n0 + rank*128, +128)
    size_t bbase = ((size_t)e * DFF + n0 + rank * 128) * H_DIM;
    run_mainloop_cg2(dyn, rowsrc, g_xh, g_xl, g_w1th, g_w1tl,
                     bbase, H_DIM, H_DIM / TBK, tmem_base, mbar0, tid, rank);

    // epilogue: warp w -> M-sub j=w>>2, lanes (w&3)*32+lane of this CTA's half
    int w = tid >> 5, lane = tid & 31;
    int j = w >> 2, pw = w & 3;
    int gm = m0 + j * 256 + (int)rank * 128 + pw * 32 + lane;
    bool ok = gm < cnt;
    size_t orow = (size_t)(off + gm) * DFF + n0;
#pragma unroll
    for (int cc = 0; cc < 8; cc++) {
        uint32_t r[32];
        tmem_ld32(r, tmem_base + j * 256 + cc * 32);
        tmem_wait_ld();
        if (ok) {
            uint32_t hw[16], lw[16];
#pragma unroll
            for (int q = 0; q < 16; q++) {
                float f0 = gelu_tanh(__uint_as_float(r[2 * q]));
                float f1 = gelu_tanh(__uint_as_float(r[2 * q + 1]));
                __nv_bfloat16 h0, l0, h1, l1;
                split2(f0, h0, l0); split2(f1, h1, l1);
                hw[q] = pack_bf2(h0, h1);
                lw[q] = pack_bf2(l0, l1);
            }
            uint4* dh = reinterpret_cast<uint4*>(&g_hh[orow + cc * 32]);
            uint4* dl = reinterpret_cast<uint4*>(&g_hl[orow + cc * 32]);
#pragma unroll
            for (int q = 0; q < 4; q++) {
                dh[q] = make_uint4(hw[4 * q], hw[4 * q + 1], hw[4 * q + 2], hw[4 * q + 3]);
                dl[q] = make_uint4(lw[4 * q], lw[4 * q + 1], lw[4 * q + 2], lw[4 * q + 3]);
            }
        }
    }
    __syncthreads();
    if (tid == 0) {
        mbar_inval(mbar0); mbar_inval(mbar0 + 8);
        mbar_inval(mbar0 + 16); mbar_inval(mbar0 + 24);
    }
    __syncthreads();
    if ((tid >> 5) == 0) tc_dealloc_cg2(tmem_base, 512);
    cluster_sync_all();
#endif
}

// GEMM2: yslot = wt * ( hmid @ w2t^T ), pair tile 512x256
__global__ __launch_bounds__(256, 1) __cluster_dims__(2, 1, 1)
void gemm2_kernel() {
#if TC_OK
    extern __shared__ __align__(1024) char dyn[];
    __shared__ __align__(16) unsigned long long mbars[4];
    __shared__ uint32_t tmem_slot;
    __shared__ size_t rowsrc[TM_CTA];
    __shared__ int   ps[TM_CTA];
    __shared__ float ws[TM_CTA];

    int e = blockIdx.z;
    int cnt = g_counts[e];
    uint32_t rank = ctarank();
    int m0 = blockIdx.y * TM_PAIR;
    if (m0 >= cnt) return;
    int n0 = (blockIdx.x >> 1) * TN;
    int off = g_off[e];
    int tid = threadIdx.x;

    uint32_t mbar0 = (uint32_t)__cvta_generic_to_shared(&mbars[0]);
    uint32_t slot  = (uint32_t)__cvta_generic_to_shared(&tmem_slot);

    if ((tid >> 5) == 0) tc_alloc_cg2(slot, 512);
    if (tid == 0) {
        mbar_init(mbar0, 1);       mbar_init(mbar0 + 8, 1);
        mbar_init(mbar0 + 16, 2);  mbar_init(mbar0 + 24, 2);
    }
    if (tid < TM_CTA) {
        int gm = m0 + ((tid >> 7) << 8) + (int)rank * 128 + (tid & 127);
        int gmc = (gm < cnt) ? gm : (cnt - 1);
        rowsrc[tid] = (size_t)(off + gmc) * DFF;
        if (gm < cnt) {
            int p = g_list[e * CAP + gm];
            ps[tid] = p; ws[tid] = g_wt[p];
        } else { ps[tid] = 0; ws[tid] = 0.0f; }
    }
    __syncthreads();
    if ((tid >> 5) == 0) tc_relinquish_cg2();
    cluster_sync_all();
    uint32_t tmem_base = tmem_slot;

    size_t bbase = ((size_t)e * H_DIM + n0 + rank * 128) * DFF;
    run_mainloop_cg2(dyn, rowsrc, g_hh, g_hl, g_w2th, g_w2tl,
                     bbase, DFF, DFF / TBK, tmem_base, mbar0, tid, rank);

    int w = tid >> 5, lane = tid & 31;
    int j = w >> 2, pw = w & 3;
    int li = j * 128 + pw * 32 + lane;     // local rowsrc index for this result row
    int gm = m0 + j * 256 + (int)rank * 128 + pw * 32 + lane;
    bool ok = gm < cnt;
    int   pp = ps[li];
    float wv = ws[li];
    float* orow = g_yslot + (size_t)pp * H_DIM + n0;
#pragma unroll
    for (int cc = 0; cc < 8; cc++) {
        uint32_t r[32];
        tmem_ld32(r, tmem_base + j * 256 + cc * 32);
        tmem_wait_ld();
        if (ok) {
            float4* dst = reinterpret_cast<float4*>(orow + cc * 32);
#pragma unroll
            for (int q = 0; q < 8; q++) {
                dst[q] = make_float4(wv * __uint_as_float(r[4 * q]),
                                     wv * __uint_as_float(r[4 * q + 1]),
                                     wv * __uint_as_float(r[4 * q + 2]),
                                     wv * __uint_as_float(r[4 * q + 3]));
            }
        }
    }
    __syncthreads();
    if (tid == 0) {
        mbar_inval(mbar0); mbar_inval(mbar0 + 8);
        mbar_inval(mbar0 + 16); mbar_inval(mbar0 + 24);
    }
    __syncthreads();
    if ((tid >> 5) == 0) tc_dealloc_cg2(tmem_base, 512);
    cluster_sync_all();
#endif
}

__global__ void combine_kernel(float* __restrict__ out) {
    size_t i = (size_t)blockIdx.x * blockDim.x + threadIdx.x;
    const size_t total = (size_t)T_TOK * (H_DIM / 4);
    if (i >= total) return;
    size_t t = i / (H_DIM / 4);
    size_t h4 = i % (H_DIM / 4);
    const float4* ys = reinterpret_cast<const float4*>(g_yslot);
    float4 a = ys[(2 * t) * (H_DIM / 4) + h4];
    float4 b = ys[(2 * t + 1) * (H_DIM / 4) + h4];
    reinterpret_cast<float4*>(out)[i] =
        make_float4(a.x + b.x, a.y + b.y, a.z + b.z, a.w + b.w);
}

// ---------------- launch ----------------
static void launch_cluster_gemm(void (*kern)(), dim3 grid) {
    cudaLaunchConfig_t cfg = {};
    cfg.gridDim = grid;
    cfg.blockDim = dim3(256, 1, 1);
    cfg.dynamicSmemBytes = SMEM_DYN;
    cfg.stream = 0;
    cudaLaunchAttribute attrs[1];
    attrs[0].id = cudaLaunchAttributeClusterDimension;
    attrs[0].val.clusterDim.x = 2;
    attrs[0].val.clusterDim.y = 1;
    attrs[0].val.clusterDim.z = 1;
    cfg.attrs = attrs;
    cfg.numAttrs = 1;
    cudaLaunchKernelEx(&cfg, kern);
}

extern "C" void kernel_launch(void* const* d_in, const int* in_sizes, int n_in,
                              void* d_out, int out_size) {
    const float* x  = (const float*)d_in[0];
    const float* wg = (const float*)d_in[1];
    const float* w1 = (const float*)d_in[2];
    const float* w2 = (const float*)d_in[3];
    float* out    = (float*)d_out;
    float* logits = out + (size_t)T_TOK * H_DIM;

    static bool attr_done = false;
    if (!attr_done) {
        cudaFuncSetAttribute(gemm1_kernel, cudaFuncAttributeMaxDynamicSharedMemorySize, SMEM_DYN);
        cudaFuncSetAttribute(gemm2_kernel, cudaFuncAttributeMaxDynamicSharedMemorySize, SMEM_DYN);
        attr_done = true;
    }

    zero_counts_kernel<<<1, 32>>>();
    router_kernel<<<T_TOK / 8, 256>>>(x, wg, logits);
    offsets_kernel<<<1, 32>>>();

    {
        __nv_bfloat16 *xh, *xl, *w1th, *w1tl, *w2th, *w2tl;
        cudaGetSymbolAddress((void**)&xh,  g_xh);
        cudaGetSymbolAddress((void**)&xl,  g_xl);
        cudaGetSymbolAddress((void**)&w1th, g_w1th);
        cudaGetSymbolAddress((void**)&w1tl, g_w1tl);
        cudaGetSymbolAddress((void**)&w2th, g_w2th);
        cudaGetSymbolAddress((void**)&w2tl, g_w2tl);

        size_t n4x = (size_t)T_TOK * H_DIM / 4;
        split_kernel<<<(unsigned)((n4x + 255) / 256), 256>>>(x, xh, xl, n4x);

        dim3 bt(32, 8);
        dim3 gt1(DFF / 32, H_DIM / 32, NE);
        transpose_split_kernel<<<gt1, bt>>>(w1, w1th, w1tl, H_DIM, DFF);
        dim3 gt2(H_DIM / 32, DFF / 32, NE);
        transpose_split_kernel<<<gt2, bt>>>(w2, w2th, w2tl, DFF, H_DIM);
    }

    // grid.x = 2 CTAs (cluster pair) per 256-col tile; grid.y = 512-row pair tiles
    dim3 g1(2 * (DFF / TN), CAP / TM_PAIR, NE);
    launch_cluster_gemm(gemm1_kernel, g1);

    dim3 g2(2 * (H_DIM / TN), CAP / TM_PAIR, NE);
    launch_cluster_gemm(gemm2_kernel, g2);

    combine_kernel<<<(T_TOK * (H_DIM / 4) + 255) / 256, 256>>>(out);
}

// round 9
// speedup vs baseline: 1.7500x; 1.7500x over previous
#include <cuda_runtime.h>
#include <cuda.h>
#include <cuda_bf16.h>
#include <cstdint>
#include <cstring>
#include <dlfcn.h>

#if defined(__CUDA_ARCH_FEAT_SM103_ALL) || defined(__CUDA_ARCH_FEAT_SM100_ALL) || defined(__CUDA_ARCH_FEAT_SM101_ALL)
#define TC_OK 1
#else
#define TC_OK 0
#endif

// ---------------- problem constants ----------------
#define T_TOK 8192
#define H_DIM 2048
#define DFF   8192
#define NE    8
#define CAP   8192
#define NPAIR (T_TOK * 2)

// ---------------- scratch (device globals) ----------------
__device__ __nv_bfloat16 g_pxh[(size_t)NPAIR * H_DIM];   // packed x rows (expert order), hi
__device__ __nv_bfloat16 g_pxl[(size_t)NPAIR * H_DIM];   // lo
__device__ __nv_bfloat16 g_w1th[(size_t)NE * DFF * H_DIM];
__device__ __nv_bfloat16 g_w1tl[(size_t)NE * DFF * H_DIM];
__device__ __nv_bfloat16 g_w2th[(size_t)NE * H_DIM * DFF];
__device__ __nv_bfloat16 g_w2tl[(size_t)NE * H_DIM * DFF];
__device__ __nv_bfloat16 g_hh[(size_t)NPAIR * DFF];
__device__ __nv_bfloat16 g_hl[(size_t)NPAIR * DFF];
__device__ float g_yslot[(size_t)NPAIR * H_DIM];
__device__ int   g_list[NE * CAP];
__device__ float g_wt[NPAIR];
__device__ int   g_counts[NE];
__device__ int   g_off[NE];

// ---------------- scalar helpers ----------------
__device__ __forceinline__ float fast_tanh(float v) {
    float r; asm("tanh.approx.f32 %0, %1;" : "=f"(r) : "f"(v)); return r;
}
__device__ __forceinline__ float gelu_tanh(float v) {
    float u = 0.7978845608028654f * (v + 0.044715f * v * v * v);
    return 0.5f * v * (1.0f + fast_tanh(u));
}
__device__ __forceinline__ uint32_t pack_bf2(__nv_bfloat16 a, __nv_bfloat16 b) {
    __nv_bfloat162 p = __halves2bfloat162(a, b);
    return *reinterpret_cast<uint32_t*>(&p);
}
__device__ __forceinline__ void split2(float v, __nv_bfloat16& h, __nv_bfloat16& l) {
    h = __float2bfloat16(v);
    l = __float2bfloat16(v - __bfloat162float(h));
}

// ---------------- family-safe PTX helpers ----------------
__device__ __forceinline__ void mbar_init(uint32_t a, uint32_t cnt) {
    asm volatile("mbarrier.init.shared.b64 [%0], %1;" :: "r"(a), "r"(cnt) : "memory");
}
__device__ __forceinline__ void mbar_inval(uint32_t a) {
    asm volatile("mbarrier.inval.shared.b64 [%0];" :: "r"(a) : "memory");
}
__device__ __forceinline__ void mbar_expect_tx(uint32_t a, uint32_t bytes) {
    asm volatile("mbarrier.arrive.expect_tx.shared.b64 _, [%0], %1;"
                 :: "r"(a), "r"(bytes) : "memory");
}
__device__ __forceinline__ void mbar_wait(uint32_t a, uint32_t parity) {
    uint32_t done;
    asm volatile("{\n\t.reg .pred p;\n\t"
                 "mbarrier.try_wait.parity.acquire.cta.shared::cta.b64 p, [%1], %2;\n\t"
                 "selp.b32 %0, 1, 0, p;\n\t}"
                 : "=r"(done) : "r"(a), "r"(parity) : "memory");
    if (!done) {
        asm volatile("{\n\t.reg .pred P1;\n\t"
                     "W_%=:\n\t"
                     "mbarrier.try_wait.parity.acquire.cta.shared::cta.b64 P1, [%0], %1, 0x989680;\n\t"
                     "@P1 bra.uni D_%=;\n\t"
                     "bra.uni W_%=;\n\t"
                     "D_%=:\n\t}"
                     :: "r"(a), "r"(parity) : "memory");
    }
}
__device__ __forceinline__ void mbar_wait_cluster(uint32_t a, uint32_t parity) {
    asm volatile("{\n\t.reg .pred P1;\n\t"
                 "W_%=:\n\t"
                 "mbarrier.try_wait.parity.acquire.cluster.shared::cta.b64 P1, [%0], %1, 0x989680;\n\t"
                 "@P1 bra.uni D_%=;\n\t"
                 "bra.uni W_%=;\n\t"
                 "D_%=:\n\t}"
                 :: "r"(a), "r"(parity) : "memory");
}
__device__ __forceinline__ void mbar_arrive_local(uint32_t a) {
    asm volatile("mbarrier.arrive.shared.b64 _, [%0];" :: "r"(a) : "memory");
}
__device__ __forceinline__ void mbar_arrive_cluster_rank(uint32_t a, uint32_t rank) {
    asm volatile("{\n\t.reg .b32 r;\n\t"
                 "mapa.shared::cluster.u32 r, %0, %1;\n\t"
                 "mbarrier.arrive.shared::cluster.b64 _, [r];\n\t}"
                 :: "r"(a), "r"(rank) : "memory");
}
__device__ __forceinline__ void cluster_sync_all() {
    asm volatile("barrier.cluster.arrive.aligned;" ::: "memory");
    asm volatile("barrier.cluster.wait.aligned;" ::: "memory");
}
__device__ __forceinline__ uint32_t ctarank() {
    uint32_t r; asm("mov.u32 %0, %%cluster_ctarank;" : "=r"(r)); return r;
}

// ---------------- routing kernels ----------------
__global__ void zero_counts_kernel() {
    if (threadIdx.x < NE) g_counts[threadIdx.x] = 0;
}

__global__ void router_kernel(const float* __restrict__ x,
                              const float* __restrict__ wg,
                              float* __restrict__ logits_out) {
    int t = blockIdx.x * (blockDim.x >> 5) + (threadIdx.x >> 5);
    int lane = threadIdx.x & 31;
    if (t >= T_TOK) return;
    const float* xr = x + (size_t)t * H_DIM;
    float acc[NE];
#pragma unroll
    for (int e = 0; e < NE; e++) acc[e] = 0.0f;
    for (int h = lane; h < H_DIM; h += 32) {
        float xv = xr[h];
        const float4* w4 = reinterpret_cast<const float4*>(wg + (size_t)h * NE);
        float4 a = w4[0], b = w4[1];
        acc[0] += xv * a.x; acc[1] += xv * a.y; acc[2] += xv * a.z; acc[3] += xv * a.w;
        acc[4] += xv * b.x; acc[5] += xv * b.y; acc[6] += xv * b.z; acc[7] += xv * b.w;
    }
#pragma unroll
    for (int e = 0; e < NE; e++)
#pragma unroll
        for (int o = 16; o > 0; o >>= 1)
            acc[e] += __shfl_xor_sync(0xffffffffu, acc[e], o);
    if (lane == 0) {
#pragma unroll
        for (int e = 0; e < NE; e++) logits_out[(size_t)t * NE + e] = acc[e];
        float m = acc[0];
#pragma unroll
        for (int e = 1; e < NE; e++) m = fmaxf(m, acc[e]);
        float p[NE], s = 0.0f;
#pragma unroll
        for (int e = 0; e < NE; e++) { p[e] = expf(acc[e] - m); s += p[e]; }
        float inv = 1.0f / s;
        int i0 = 0;
#pragma unroll
        for (int e = 1; e < NE; e++) if (acc[e] > acc[i0]) i0 = e;
        int i1 = (i0 == 0) ? 1 : 0;
#pragma unroll
        for (int e = 0; e < NE; e++) if (e != i0 && acc[e] > acc[i1]) i1 = e;
        int p0 = t * 2, p1 = t * 2 + 1;
        g_wt[p0] = p[i0] * inv;
        g_wt[p1] = p[i1] * inv;
        int pos0 = atomicAdd(&g_counts[i0], 1);
        g_list[i0 * CAP + pos0] = p0;
        int pos1 = atomicAdd(&g_counts[i1], 1);
        g_list[i1 * CAP + pos1] = p1;
    }
}

__global__ void offsets_kernel() {
    if (threadIdx.x == 0) {
        int s = 0;
#pragma unroll
        for (int e = 0; e < NE; e++) { g_off[e] = s; s += g_counts[e]; }
    }
}

// ---------------- pack x rows into expert order + split fp32->bf16 hi/lo ----------------
__global__ void pack_x_kernel(const float* __restrict__ x) {
    int e = blockIdx.y, m = blockIdx.x;
    if (m >= g_counts[e]) return;
    int r = g_off[e] + m;
    int tok = g_list[e * CAP + m] >> 1;
    const float4* src = reinterpret_cast<const float4*>(x + (size_t)tok * H_DIM);
    uint2* dh = reinterpret_cast<uint2*>(g_pxh + (size_t)r * H_DIM);
    uint2* dl = reinterpret_cast<uint2*>(g_pxl + (size_t)r * H_DIM);
    for (int i = threadIdx.x; i < H_DIM / 4; i += blockDim.x) {
        float4 v = src[i];
        __nv_bfloat16 h0, l0, h1, l1, h2, l2, h3, l3;
        split2(v.x, h0, l0); split2(v.y, h1, l1);
        split2(v.z, h2, l2); split2(v.w, h3, l3);
        dh[i] = make_uint2(pack_bf2(h0, h1), pack_bf2(h2, h3));
        dl[i] = make_uint2(pack_bf2(l0, l1), pack_bf2(l2, l3));
    }
}

// ---------------- transpose + split: W[e][K][N] -> Wt(h/l)[e][N][K] ----------------
__global__ void transpose_split_kernel(const float* __restrict__ src,
                                       __nv_bfloat16* __restrict__ dh,
                                       __nv_bfloat16* __restrict__ dl,
                                       int K, int N) {
    __shared__ float tile[32][33];
    int e = blockIdx.z;
    const float* S = src + (size_t)e * K * N;
    int n0 = blockIdx.x * 32, k0 = blockIdx.y * 32;
#pragma unroll
    for (int i = threadIdx.y; i < 32; i += 8)
        tile[i][threadIdx.x] = S[(size_t)(k0 + i) * N + n0 + threadIdx.x];
    __syncthreads();
    __nv_bfloat16* Dh = dh + (size_t)e * K * N;
    __nv_bfloat16* Dl = dl + (size_t)e * K * N;
#pragma unroll
    for (int i = threadIdx.y; i < 32; i += 8) {
        float v = tile[threadIdx.x][i];
        __nv_bfloat16 h, l;
        split2(v, h, l);
        size_t o = (size_t)(n0 + i) * K + k0 + threadIdx.x;
        Dh[o] = h;
        Dl[o] = l;
    }
}

// ---------------- cg2 + TMA GEMM: pair tile 512x256, BK=64 (SW128), 2 stages ----------------
#define TM_PAIR 512
#define TN      256
#define TBK     64            // 64 bf16 = 128B row (SW128 atom width)
// per-CTA stage layout (bytes):
#define ST_AH0  0             // A hi, rows block0 (128 x 128B)
#define ST_AH1  16384         // A hi, rows block1
#define ST_AL0  32768
#define ST_AL1  49152
#define ST_BH   65536         // B hi (128 x 128B)
#define ST_BL   81920
#define STAGE_BYTES 98304
#define SMEM_DYN (2 * STAGE_BYTES)   // 196608
#define TX_BYTES 98304

#if TC_OK
__device__ __forceinline__ uint64_t sw128_desc(uint32_t addr) {
    uint64_t d = 0;
    d |= (uint64_t)((addr >> 4) & 0x3FFF);
    d |= (uint64_t)1  << 16;   // LBO = 1 (16B)
    d |= (uint64_t)64 << 32;   // SBO = 64 (1024B = 8 rows x 128B)
    d |= (uint64_t)1  << 46;   // version = 1
    d |= (uint64_t)2  << 61;   // layout = SW128
    return d;
}

// idesc kind::f16 cg2: dtype F32, a/b BF16, M=256 (16<<24), N=256 (32<<17)
#define IDESC_CG2 ((16u << 24) | (32u << 17) | (1u << 10) | (1u << 7) | (1u << 4))

__device__ __forceinline__ void mma_f16_ss_cg2(uint32_t d, uint64_t ad, uint64_t bd,
                                               uint32_t en) {
    asm volatile(
        "{\n\t.reg .pred p;\n\tsetp.ne.u32 p, %4, 0;\n\t"
        "tcgen05.mma.cta_group::2.kind::f16 [%0], %1, %2, %3, "
        "{%5,%5,%5,%5,%5,%5,%5,%5}, p;\n\t}"
        :: "r"(d), "l"(ad), "l"(bd), "r"(IDESC_CG2), "r"(en), "r"(0u) : "memory");
}
__device__ __forceinline__ void tc_alloc_cg2(uint32_t smem_slot, uint32_t ncols) {
    asm volatile("tcgen05.alloc.cta_group::2.sync.aligned.shared::cta.b32 [%0], %1;"
                 :: "r"(smem_slot), "r"(ncols) : "memory");
}
__device__ __forceinline__ void tc_relinquish_cg2() {
    asm volatile("tcgen05.relinquish_alloc_permit.cta_group::2.sync.aligned;");
}
__device__ __forceinline__ void tc_dealloc_cg2(uint32_t tmem, uint32_t ncols) {
    asm volatile("tcgen05.dealloc.cta_group::2.sync.aligned.b32 %0, %1;"
                 :: "r"(tmem), "r"(ncols));
}
__device__ __forceinline__ void tc_commit_mc_cg2(uint32_t mbar, uint16_t mask) {
    asm volatile("tcgen05.commit.cta_group::2.mbarrier::arrive::one.shared::cluster.multicast::cluster.b64 [%0], %1;"
                 :: "r"(mbar), "h"(mask) : "memory");
}
__device__ __forceinline__ void tc_fence_after() {
    asm volatile("tcgen05.fence::after_thread_sync;" ::: "memory");
}
__device__ __forceinline__ void tmem_ld32(uint32_t* r, uint32_t addr) {
    asm volatile(
        "tcgen05.ld.sync.aligned.32x32b.x32.b32 "
        "{%0,%1,%2,%3,%4,%5,%6,%7,%8,%9,%10,%11,%12,%13,%14,%15,"
        "%16,%17,%18,%19,%20,%21,%22,%23,%24,%25,%26,%27,%28,%29,%30,%31}, [%32];"
        : "=r"(r[0]), "=r"(r[1]), "=r"(r[2]), "=r"(r[3]), "=r"(r[4]), "=r"(r[5]),
          "=r"(r[6]), "=r"(r[7]), "=r"(r[8]), "=r"(r[9]), "=r"(r[10]), "=r"(r[11]),
          "=r"(r[12]), "=r"(r[13]), "=r"(r[14]), "=r"(r[15]), "=r"(r[16]), "=r"(r[17]),
          "=r"(r[18]), "=r"(r[19]), "=r"(r[20]), "=r"(r[21]), "=r"(r[22]), "=r"(r[23]),
          "=r"(r[24]), "=r"(r[25]), "=r"(r[26]), "=r"(r[27]), "=r"(r[28]), "=r"(r[29]),
          "=r"(r[30]), "=r"(r[31])
        : "r"(addr));
}
__device__ __forceinline__ void tmem_wait_ld() {
    asm volatile("tcgen05.wait::ld.sync.aligned;" ::: "memory");
}
__device__ __forceinline__ void tma2d(uint32_t smem, const CUtensorMap* m,
                                      int cx, int cy, uint32_t mbar) {
    asm volatile(
        "cp.async.bulk.tensor.2d.shared::cta.global.tile.mbarrier::complete_tx::bytes "
        "[%0], [%1, {%2, %3}], [%4];"
        :: "r"(smem), "l"(m), "r"(cx), "r"(cy), "r"(mbar) : "memory");
}

// mbar layout (u64 idx): 0,1 done[s] (cnt 1); 2,3 full[s] (cnt 1, tx); 4,5 ready[s] (cnt 2)
#define BAR_DONE(s)  (mbar0 + (uint32_t)(s) * 8)
#define BAR_FULL(s)  (mbar0 + 16 + (uint32_t)(s) * 8)
#define BAR_READY(s) (mbar0 + 32 + (uint32_t)(s) * 8)

// issue one stage's 6 TMA loads into this CTA's smem (single thread)
__device__ __forceinline__ void issue_stage_tma(
    uint32_t dynb, int s, int kt,
    const CUtensorMap* ah, const CUtensorMap* al,
    const CUtensorMap* bh, const CUtensorMap* bl,
    int ar0, int ar1, int br0, uint32_t fullbar)
{
    uint32_t base = dynb + (uint32_t)s * STAGE_BYTES;
    mbar_expect_tx(fullbar, TX_BYTES);
    tma2d(base + ST_AH0, ah, kt, ar0, fullbar);
    tma2d(base + ST_AH1, ah, kt, ar1, fullbar);
    tma2d(base + ST_AL0, al, kt, ar0, fullbar);
    tma2d(base + ST_AL1, al, kt, ar1, fullbar);
    tma2d(base + ST_BH,  bh, kt, br0, fullbar);
    tma2d(base + ST_BL,  bl, kt, br0, fullbar);
}

// pipelined cg2 mainloop, driven by tid 0 of each CTA; on return TMEM D ready
__device__ __forceinline__ void run_loop_tma(
    uint32_t dynb,
    const CUtensorMap* ah, const CUtensorMap* al,
    const CUtensorMap* bh, const CUtensorMap* bl,
    int ar0, int ar1, int br0, int KIT,
    uint32_t tmem_base, uint32_t mbar0, int tid, uint32_t rank)
{
    if (tid == 0) {
        // prologue: fill stages 0 and 1 locally
        issue_stage_tma(dynb, 0, 0, ah, al, bh, bl, ar0, ar1, br0, BAR_FULL(0));
        issue_stage_tma(dynb, 1, TBK, ah, al, bh, bl, ar0, ar1, br0, BAR_FULL(1));
    }

    if (tid == 0 && rank == 0) {
        // ---- leader: MMA issue + own refills ----
        int pf[2] = {0, 0}, pr[2] = {0, 0}, pd[2] = {0, 0};
        for (int ki = 0; ki < KIT; ki++) {
            int s = ki & 1;
            mbar_wait(BAR_FULL(s), pf[s]); pf[s] ^= 1;
            mbar_arrive_local(BAR_READY(s));
            mbar_wait_cluster(BAR_READY(s), pr[s]); pr[s] ^= 1;
            uint32_t base = dynb + (uint32_t)s * STAGE_BYTES;
            uint64_t dAh = sw128_desc(base);
            uint64_t dAl = sw128_desc(base + ST_AL0);
            uint64_t dBh = sw128_desc(base + ST_BH);
            uint64_t dBl = sw128_desc(base + ST_BL);
#pragma unroll
            for (int sub = 0; sub < 2; sub++) {
                uint32_t d = tmem_base + sub * 256;
                uint32_t ao = sub * 1024;   // +16KB in 16B units
#pragma unroll
                for (int c = 0; c < 4; c++) {
                    uint32_t off = c * 2;
                    uint32_t en0 = (ki > 0 || c > 0) ? 1u : 0u;
                    mma_f16_ss_cg2(d, dAh + ao + off, dBh + off, en0);
                    mma_f16_ss_cg2(d, dAl + ao + off, dBh + off, 1u);
                    mma_f16_ss_cg2(d, dAh + ao + off, dBl + off, 1u);
                }
            }
            tc_commit_mc_cg2(BAR_DONE(s), 0x3);
            if (ki + 2 < KIT) {
                mbar_wait(BAR_DONE(s), pd[s]); pd[s] ^= 1;
                issue_stage_tma(dynb, s, (ki + 2) * TBK, ah, al, bh, bl,
                                ar0, ar1, br0, BAR_FULL(s));
            }
        }
        int sl = (KIT - 1) & 1;
        mbar_wait(BAR_DONE(sl), pd[sl]);
    } else if (tid == 0) {
        // ---- rank-1 relay + own refills ----
        int pf[2] = {0, 0}, pd[2] = {0, 0};
        for (int ki = 0; ki < KIT; ki++) {
            int s = ki & 1;
            mbar_wait(BAR_FULL(s), pf[s]); pf[s] ^= 1;
            mbar_arrive_cluster_rank(BAR_READY(s), 0);
            if (ki + 2 < KIT) {
                mbar_wait(BAR_DONE(s), pd[s]); pd[s] ^= 1;
                issue_stage_tma(dynb, s, (ki + 2) * TBK, ah, al, bh, bl,
                                ar0, ar1, br0, BAR_FULL(s));
            }
        }
        int sl = (KIT - 1) & 1;
        mbar_wait(BAR_DONE(sl), pd[sl]);
    }
    __syncthreads();
    tc_fence_after();
}
#endif  // TC_OK

// GEMM1: hmid(hi/lo) = split(gelu( px @ w1t^T )), pair tile 512x256
__global__ __launch_bounds__(256, 1) __cluster_dims__(2, 1, 1)
void gemm1_kernel(const __grid_constant__ CUtensorMap tmah,
                  const __grid_constant__ CUtensorMap tmal,
                  const __grid_constant__ CUtensorMap tmbh,
                  const __grid_constant__ CUtensorMap tmbl) {
#if TC_OK
    extern __shared__ __align__(1024) char dyn[];
    __shared__ __align__(16) unsigned long long mbars[6];
    __shared__ uint32_t tmem_slot;

    int e = blockIdx.z;
    int cnt = g_counts[e];
    uint32_t rank = ctarank();
    int m0 = blockIdx.y * TM_PAIR;
    if (m0 >= cnt) return;
    int n0 = (blockIdx.x >> 1) * TN;
    int off = g_off[e];
    int tid = threadIdx.x;

    uint32_t mbar0 = (uint32_t)__cvta_generic_to_shared(&mbars[0]);
    uint32_t slot  = (uint32_t)__cvta_generic_to_shared(&tmem_slot);
    uint32_t dynb  = (uint32_t)__cvta_generic_to_shared(dyn);

    if ((tid >> 5) == 0) tc_alloc_cg2(slot, 512);
    if (tid == 0) {
        mbar_init(BAR_DONE(0), 1);  mbar_init(BAR_DONE(1), 1);
        mbar_init(BAR_FULL(0), 1);  mbar_init(BAR_FULL(1), 1);
        mbar_init(BAR_READY(0), 2); mbar_init(BAR_READY(1), 2);
    }
    __syncthreads();
    if ((tid >> 5) == 0) tc_relinquish_cg2();
    cluster_sync_all();
    uint32_t tmem_base = tmem_slot;

    int ar0 = off + m0 + (int)rank * 128;   // rows of packed-x (global packed index)
    int ar1 = ar0 + 256;
    int br0 = e * DFF + n0 + (int)rank * 128;

    run_loop_tma(dynb, &tmah, &tmal, &tmbh, &tmbl, ar0, ar1, br0,
                 H_DIM / TBK, tmem_base, mbar0, tid, rank);

    // epilogue: gelu + split -> bf16 hi/lo hmid
    int w = tid >> 5, lane = tid & 31;
    int j = w >> 2, pw = w & 3;
    int gm = m0 + j * 256 + (int)rank * 128 + pw * 32 + lane;
    bool ok = gm < cnt;
    size_t orow = (size_t)(off + gm) * DFF + n0;
#pragma unroll
    for (int cc = 0; cc < 8; cc++) {
        uint32_t r[32];
        tmem_ld32(r, tmem_base + j * 256 + cc * 32);
        tmem_wait_ld();
        if (ok) {
            uint32_t hw[16], lw[16];
#pragma unroll
            for (int q = 0; q < 16; q++) {
                float f0 = gelu_tanh(__uint_as_float(r[2 * q]));
                float f1 = gelu_tanh(__uint_as_float(r[2 * q + 1]));
                __nv_bfloat16 h0, l0, h1, l1;
                split2(f0, h0, l0); split2(f1, h1, l1);
                hw[q] = pack_bf2(h0, h1);
                lw[q] = pack_bf2(l0, l1);
            }
            uint4* dh = reinterpret_cast<uint4*>(&g_hh[orow + cc * 32]);
            uint4* dl = reinterpret_cast<uint4*>(&g_hl[orow + cc * 32]);
#pragma unroll
            for (int q = 0; q < 4; q++) {
                dh[q] = make_uint4(hw[4 * q], hw[4 * q + 1], hw[4 * q + 2], hw[4 * q + 3]);
                dl[q] = make_uint4(lw[4 * q], lw[4 * q + 1], lw[4 * q + 2], lw[4 * q + 3]);
            }
        }
    }
    __syncthreads();
    if (tid == 0) {
        mbar_inval(BAR_DONE(0)); mbar_inval(BAR_DONE(1));
        mbar_inval(BAR_FULL(0)); mbar_inval(BAR_FULL(1));
        mbar_inval(BAR_READY(0)); mbar_inval(BAR_READY(1));
    }
    __syncthreads();
    if ((tid >> 5) == 0) tc_dealloc_cg2(tmem_base, 512);
    cluster_sync_all();
#endif
}

// GEMM2: yslot = wt * ( hmid @ w2t^T ), pair tile 512x256
__global__ __launch_bounds__(256, 1) __cluster_dims__(2, 1, 1)
void gemm2_kernel(const __grid_constant__ CUtensorMap tmah,
                  const __grid_constant__ CUtensorMap tmal,
                  const __grid_constant__ CUtensorMap tmbh,
                  const __grid_constant__ CUtensorMap tmbl) {
#if TC_OK
    extern __shared__ __align__(1024) char dyn[];
    __shared__ __align__(16) unsigned long long mbars[6];
    __shared__ uint32_t tmem_slot;
    __shared__ int   ps[256];
    __shared__ float ws[256];

    int e = blockIdx.z;
    int cnt = g_counts[e];
    uint32_t rank = ctarank();
    int m0 = blockIdx.y * TM_PAIR;
    if (m0 >= cnt) return;
    int n0 = (blockIdx.x >> 1) * TN;
    int off = g_off[e];
    int tid = threadIdx.x;

    uint32_t mbar0 = (uint32_t)__cvta_generic_to_shared(&mbars[0]);
    uint32_t slot  = (uint32_t)__cvta_generic_to_shared(&tmem_slot);
    uint32_t dynb  = (uint32_t)__cvta_generic_to_shared(dyn);

    if ((tid >> 5) == 0) tc_alloc_cg2(slot, 512);
    if (tid == 0) {
        mbar_init(BAR_DONE(0), 1);  mbar_init(BAR_DONE(1), 1);
        mbar_init(BAR_FULL(0), 1);  mbar_init(BAR_FULL(1), 1);
        mbar_init(BAR_READY(0), 2); mbar_init(BAR_READY(1), 2);
    }
    {
        int gm = m0 + ((tid >> 7) << 8) + (int)rank * 128 + (tid & 127);
        if (gm < cnt) {
            int p = g_list[e * CAP + gm];
            ps[tid] = p; ws[tid] = g_wt[p];
        } else { ps[tid] = 0; ws[tid] = 0.0f; }
    }
    __syncthreads();
    if ((tid >> 5) == 0) tc_relinquish_cg2();
    cluster_sync_all();
    uint32_t tmem_base = tmem_slot;

    int ar0 = off + m0 + (int)rank * 128;   // rows of g_hh (packed)
    int ar1 = ar0 + 256;
    int br0 = e * H_DIM + n0 + (int)rank * 128;

    run_loop_tma(dynb, &tmah, &tmal, &tmbh, &tmbl, ar0, ar1, br0,
                 DFF / TBK, tmem_base, mbar0, tid, rank);

    int w = tid >> 5, lane = tid & 31;
    int j = w >> 2, pw = w & 3;
    int li = j * 128 + pw * 32 + lane;
    int gm = m0 + j * 256 + (int)rank * 128 + pw * 32 + lane;
    bool ok = gm < cnt;
    int   pp = ps[li];
    float wv = ws[li];
    float* orow = g_yslot + (size_t)pp * H_DIM + n0;
#pragma unroll
    for (int cc = 0; cc < 8; cc++) {
        uint32_t r[32];
        tmem_ld32(r, tmem_base + j * 256 + cc * 32);
        tmem_wait_ld();
        if (ok) {
            float4* dst = reinterpret_cast<float4*>(orow + cc * 32);
#pragma unroll
            for (int q = 0; q < 8; q++) {
                dst[q] = make_float4(wv * __uint_as_float(r[4 * q]),
                                     wv * __uint_as_float(r[4 * q + 1]),
                                     wv * __uint_as_float(r[4 * q + 2]),
                                     wv * __uint_as_float(r[4 * q + 3]));
            }
        }
    }
    __syncthreads();
    if (tid == 0) {
        mbar_inval(BAR_DONE(0)); mbar_inval(BAR_DONE(1));
        mbar_inval(BAR_FULL(0)); mbar_inval(BAR_FULL(1));
        mbar_inval(BAR_READY(0)); mbar_inval(BAR_READY(1));
    }
    __syncthreads();
    if ((tid >> 5) == 0) tc_dealloc_cg2(tmem_base, 512);
    cluster_sync_all();
#endif
}

__global__ void combine_kernel(float* __restrict__ out) {
    size_t i = (size_t)blockIdx.x * blockDim.x + threadIdx.x;
    const size_t total = (size_t)T_TOK * (H_DIM / 4);
    if (i >= total) return;
    size_t t = i / (H_DIM / 4);
    size_t h4 = i % (H_DIM / 4);
    const float4* ys = reinterpret_cast<const float4*>(g_yslot);
    float4 a = ys[(2 * t) * (H_DIM / 4) + h4];
    float4 b = ys[(2 * t + 1) * (H_DIM / 4) + h4];
    reinterpret_cast<float4*>(out)[i] =
        make_float4(a.x + b.x, a.y + b.y, a.z + b.z, a.w + b.w);
}

// ---------------- host: tensor maps via robust driver entry point ----------------
typedef CUresult (*tmap_encode_fn)(
    CUtensorMap*, CUtensorMapDataType, cuuint32_t, void*,
    const cuuint64_t*, const cuuint64_t*, const cuuint32_t*, const cuuint32_t*,
    CUtensorMapInterleave, CUtensorMapSwizzle, CUtensorMapL2promotion,
    CUtensorMapFloatOOBfill);

static tmap_encode_fn get_encoder() {
    static tmap_encode_fn fn = nullptr;
    static bool tried = false;
    if (tried) return fn;
    tried = true;
    // 1) supported route: cudart driver-entry-point query
    void* p = nullptr;
#if CUDART_VERSION >= 12000
    cudaDriverEntryPointQueryResult qr;
    if (cudaGetDriverEntryPoint("cuTensorMapEncodeTiled", &p,
                                cudaEnableDefault, &qr) == cudaSuccess &&
        qr == cudaDriverEntryPointSuccess && p) {
        fn = (tmap_encode_fn)p;
        return fn;
    }
#endif
    // 2) fallback: dlopen libcuda directly
    void* h = dlopen("libcuda.so.1", RTLD_LAZY | RTLD_GLOBAL);
    if (!h) h = dlopen("libcuda.so", RTLD_LAZY | RTLD_GLOBAL);
    if (h) {
        p = dlsym(h, "cuTensorMapEncodeTiled");
        if (p) { fn = (tmap_encode_fn)p; return fn; }
    }
    // 3) last resort: default namespace
    p = dlsym(RTLD_DEFAULT, "cuTensorMapEncodeTiled");
    if (p) fn = (tmap_encode_fn)p;
    return fn;
}

static bool enc2d(tmap_encode_fn f, CUtensorMap* m, void* p,
                  unsigned long long d0, unsigned long long d1) {
    memset(m, 0, sizeof(*m));
    if (!f) return false;
    cuuint64_t dims[2] = {d0, d1};
    cuuint64_t st[1]   = {d0 * 2};
    cuuint32_t box[2]  = {64, 128};
    cuuint32_t es[2]   = {1, 1};
    return f(m, CU_TENSOR_MAP_DATA_TYPE_BFLOAT16, 2, p, dims, st, box, es,
             CU_TENSOR_MAP_INTERLEAVE_NONE, CU_TENSOR_MAP_SWIZZLE_128B,
             CU_TENSOR_MAP_L2_PROMOTION_L2_128B,
             CU_TENSOR_MAP_FLOAT_OOB_FILL_NONE) == CUDA_SUCCESS;
}

static void launch_cluster_gemm(
    void (*kern)(const __grid_constant__ CUtensorMap, const __grid_constant__ CUtensorMap,
                 const __grid_constant__ CUtensorMap, const __grid_constant__ CUtensorMap),
    dim3 grid, const CUtensorMap& a, const CUtensorMap& b,
    const CUtensorMap& c, const CUtensorMap& d) {
    cudaLaunchConfig_t cfg = {};
    cfg.gridDim = grid;
    cfg.blockDim = dim3(256, 1, 1);
    cfg.dynamicSmemBytes = SMEM_DYN;
    cfg.stream = 0;
    cudaLaunchAttribute attrs[1];
    attrs[0].id = cudaLaunchAttributeClusterDimension;
    attrs[0].val.clusterDim.x = 2;
    attrs[0].val.clusterDim.y = 1;
    attrs[0].val.clusterDim.z = 1;
    cfg.attrs = attrs;
    cfg.numAttrs = 1;
    cudaLaunchKernelEx(&cfg, kern, a, b, c, d);
}

extern "C" void kernel_launch(void* const* d_in, const int* in_sizes, int n_in,
                              void* d_out, int out_size) {
    const float* x  = (const float*)d_in[0];
    const float* wg = (const float*)d_in[1];
    const float* w1 = (const float*)d_in[2];
    const float* w2 = (const float*)d_in[3];
    float* out    = (float*)d_out;
    float* logits = out + (size_t)T_TOK * H_DIM;

    static bool attr_done = false;
    if (!attr_done) {
        cudaFuncSetAttribute(gemm1_kernel, cudaFuncAttributeMaxDynamicSharedMemorySize, SMEM_DYN);
        cudaFuncSetAttribute(gemm2_kernel, cudaFuncAttributeMaxDynamicSharedMemorySize, SMEM_DYN);
        attr_done = true;
    }

    void *pxh, *pxl, *w1th, *w1tl, *w2th, *w2tl, *hh, *hl;
    cudaGetSymbolAddress(&pxh,  g_pxh);
    cudaGetSymbolAddress(&pxl,  g_pxl);
    cudaGetSymbolAddress(&w1th, g_w1th);
    cudaGetSymbolAddress(&w1tl, g_w1tl);
    cudaGetSymbolAddress(&w2th, g_w2th);
    cudaGetSymbolAddress(&w2tl, g_w2tl);
    cudaGetSymbolAddress(&hh,   g_hh);
    cudaGetSymbolAddress(&hl,   g_hl);

    tmap_encode_fn enc = get_encoder();
    CUtensorMap mA1h, mA1l, mB1h, mB1l, mA2h, mA2l, mB2h, mB2l;
    bool ok = true;
    ok &= enc2d(enc, &mA1h, pxh,  H_DIM, NPAIR);
    ok &= enc2d(enc, &mA1l, pxl,  H_DIM, NPAIR);
    ok &= enc2d(enc, &mB1h, w1th, H_DIM, (unsigned long long)NE * DFF);
    ok &= enc2d(enc, &mB1l, w1tl, H_DIM, (unsigned long long)NE * DFF);
    ok &= enc2d(enc, &mA2h, hh,   DFF,   NPAIR);
    ok &= enc2d(enc, &mA2l, hl,   DFF,   NPAIR);
    ok &= enc2d(enc, &mB2h, w2th, DFF,   (unsigned long long)NE * H_DIM);
    ok &= enc2d(enc, &mB2l, w2tl, DFF,   (unsigned long long)NE * H_DIM);
    if (!ok) return;   // diagnosable: all-poison output instead of SIGSEGV

    zero_counts_kernel<<<1, 32>>>();
    router_kernel<<<T_TOK / 8, 256>>>(x, wg, logits);
    offsets_kernel<<<1, 32>>>();

    {
        dim3 gp(CAP, NE);
        pack_x_kernel<<<gp, 256>>>(x);

        dim3 bt(32, 8);
        dim3 gt1(DFF / 32, H_DIM / 32, NE);
        transpose_split_kernel<<<gt1, bt>>>(w1, (__nv_bfloat16*)w1th, (__nv_bfloat16*)w1tl, H_DIM, DFF);
        dim3 gt2(H_DIM / 32, DFF / 32, NE);
        transpose_split_kernel<<<gt2, bt>>>(w2, (__nv_bfloat16*)w2th, (__nv_bfloat16*)w2tl, DFF, H_DIM);
    }

    dim3 g1(2 * (DFF / TN), CAP / TM_PAIR, NE);
    launch_cluster_gemm(gemm1_kernel, g1, mA1h, mA1l, mB1h, mB1l);

    dim3 g2(2 * (H_DIM / TN), CAP / TM_PAIR, NE);
    launch_cluster_gemm(gemm2_kernel, g2, mA2h, mA2l, mB2h, mB2l);

    combine_kernel<<<(T_TOK * (H_DIM / 4) + 255) / 256, 256>>>(out);
}